// round 1
// baseline (speedup 1.0000x reference)
#include <cuda_runtime.h>
#include <cuda_bf16.h>
#include <math.h>

// Problem constants
#define BB 4
#define TT 2048
#define CC 1024
#define HH 16
#define HD 64
#define BT (BB*TT)          // 8192

// Scratch (device globals: allocation-free per harness rules)
__device__ float g_qkv[(size_t)BT * 3 * CC];   // [B*T, 3C]
__device__ float g_att[(size_t)BT * CC];       // [B*T, C]

// ---------------------------------------------------------------------------
// SGEMM with bias: C[M,N] = A[M,K] @ B[K,N] + bias[N]
// BM=BN=128, BK=8, 256 threads, 8x8 micro-tile per thread.
// Assumes M%128==0, N%128==0, K%8==0 (true for all shapes here).
// ---------------------------------------------------------------------------
__global__ __launch_bounds__(256) void sgemm_bias(
    const float* __restrict__ A, const float* __restrict__ B,
    const float* __restrict__ bias, float* __restrict__ C,
    int M, int N, int K)
{
    __shared__ float As[8][128];
    __shared__ float Bs[8][128];

    const int tid = threadIdx.x;
    const int tx = tid & 15;          // 0..15 (col group)
    const int ty = tid >> 4;          // 0..15 (row group)
    const int rowBase = blockIdx.y * 128;
    const int colBase = blockIdx.x * 128;

    // A load mapping: 128 rows x 8 k = 256 float4 (one per thread)
    const int aRow = tid >> 1;
    const int aK4  = (tid & 1) * 4;
    // B load mapping: 8 k x 128 cols = 256 float4
    const int bK  = tid >> 5;
    const int bC4 = (tid & 31) * 4;

    float acc[8][8];
#pragma unroll
    for (int i = 0; i < 8; i++)
#pragma unroll
        for (int j = 0; j < 8; j++) acc[i][j] = 0.0f;

    for (int k0 = 0; k0 < K; k0 += 8) {
        float4 av = *(const float4*)&A[(size_t)(rowBase + aRow) * K + k0 + aK4];
        As[aK4 + 0][aRow] = av.x;
        As[aK4 + 1][aRow] = av.y;
        As[aK4 + 2][aRow] = av.z;
        As[aK4 + 3][aRow] = av.w;
        float4 bv = *(const float4*)&B[(size_t)(k0 + bK) * N + colBase + bC4];
        *(float4*)&Bs[bK][bC4] = bv;
        __syncthreads();

#pragma unroll
        for (int kk = 0; kk < 8; kk++) {
            float ra[8], rb[8];
#pragma unroll
            for (int i = 0; i < 8; i++) ra[i] = As[kk][ty * 8 + i];
#pragma unroll
            for (int j = 0; j < 8; j++) rb[j] = Bs[kk][tx * 8 + j];
#pragma unroll
            for (int i = 0; i < 8; i++)
#pragma unroll
                for (int j = 0; j < 8; j++) acc[i][j] += ra[i] * rb[j];
        }
        __syncthreads();
    }

#pragma unroll
    for (int i = 0; i < 8; i++) {
        int r = rowBase + ty * 8 + i;
#pragma unroll
        for (int j4 = 0; j4 < 8; j4 += 4) {
            int c = colBase + tx * 8 + j4;
            float4 o;
            o.x = acc[i][j4 + 0] + bias[c + 0];
            o.y = acc[i][j4 + 1] + bias[c + 1];
            o.z = acc[i][j4 + 2] + bias[c + 2];
            o.w = acc[i][j4 + 3] + bias[c + 3];
            *(float4*)&C[(size_t)r * N + c] = o;
        }
    }
}

// ---------------------------------------------------------------------------
// Causal flash attention.
// Grid: (T/64, H, B). Block: 256 threads = 64 rows x 4 threads/row.
// Each thread owns 16 strided columns (c = lane4 + 4*i).
// smem tiles Q/K/V/S: 64 x 64 fp32, row stride 68 (bank-friendly, float4-able).
// ---------------------------------------------------------------------------
#define LDT 68
#define ATTN_SMEM (4 * 64 * LDT * (int)sizeof(float))

__global__ __launch_bounds__(256) void attn_kernel(
    const float* __restrict__ qkv, float* __restrict__ out)
{
    extern __shared__ float sm[];
    float* Qs = sm;
    float* Ks = sm + 64 * LDT;
    float* Vs = sm + 2 * 64 * LDT;
    float* Ss = sm + 3 * 64 * LDT;

    const int it = blockIdx.x;     // q tile
    const int h  = blockIdx.y;
    const int b  = blockIdx.z;
    const int tid = threadIdx.x;

    const size_t rowStride = 3 * CC;
    const float* qbase = qkv + (size_t)b * TT * rowStride + (size_t)h * HD;
    const float* kbase = qbase + CC;
    const float* vbase = qbase + 2 * CC;

    // --- load Q tile (64 rows x 64 floats = 1024 float4, 4 per thread) ---
#pragma unroll
    for (int i = 0; i < 4; i++) {
        int idx = tid + i * 256;
        int row = idx >> 4;           // 0..63
        int v4  = (idx & 15) * 4;     // 0..60
        float4 qv = *(const float4*)&qbase[(size_t)(it * 64 + row) * rowStride + v4];
        *(float4*)&Qs[row * LDT + v4] = qv;
    }

    const int r     = tid >> 2;       // row 0..63
    const int lane4 = tid & 3;        // 0..3

    float o[16];
#pragma unroll
    for (int i = 0; i < 16; i++) o[i] = 0.0f;
    float m_run = -1e30f;
    float l_run = 0.0f;
    const float scale = 0.125f;       // 1/sqrt(64)

    for (int jt = 0; jt <= it; jt++) {
        __syncthreads();   // previous iteration done with K/V/S
        // load K,V tiles
#pragma unroll
        for (int i = 0; i < 4; i++) {
            int idx = tid + i * 256;
            int row = idx >> 4;
            int v4  = (idx & 15) * 4;
            size_t goff = (size_t)(jt * 64 + row) * rowStride + v4;
            *(float4*)&Ks[row * LDT + v4] = *(const float4*)&kbase[goff];
            *(float4*)&Vs[row * LDT + v4] = *(const float4*)&vbase[goff];
        }
        __syncthreads();

        // --- S = scale * Q K^T for this thread's 16 columns ---
        float s[16];
#pragma unroll
        for (int i = 0; i < 16; i++) s[i] = 0.0f;
#pragma unroll 8
        for (int d = 0; d < 64; d++) {
            float qd = Qs[r * LDT + d];
#pragma unroll
            for (int i = 0; i < 16; i++) {
                int c = lane4 + 4 * i;
                s[i] += qd * Ks[c * LDT + d];
            }
        }

        // scale + causal mask (only needed on diagonal tile)
        if (jt == it) {
#pragma unroll
            for (int i = 0; i < 16; i++) {
                int c = lane4 + 4 * i;
                s[i] = (c > r) ? -1e30f : s[i] * scale;
            }
        } else {
#pragma unroll
            for (int i = 0; i < 16; i++) s[i] *= scale;
        }

        // --- online softmax update ---
        float mloc = -1e30f;
#pragma unroll
        for (int i = 0; i < 16; i++) mloc = fmaxf(mloc, s[i]);
        mloc = fmaxf(mloc, __shfl_xor_sync(0xffffffffu, mloc, 1));
        mloc = fmaxf(mloc, __shfl_xor_sync(0xffffffffu, mloc, 2));
        float m_new = fmaxf(m_run, mloc);
        float corr = __expf(m_run - m_new);
        l_run *= corr;
#pragma unroll
        for (int i = 0; i < 16; i++) o[i] *= corr;

        float psum = 0.0f;
#pragma unroll
        for (int i = 0; i < 16; i++) {
            float p = __expf(s[i] - m_new);
            psum += p;
            Ss[r * LDT + lane4 + 4 * i] = p;
        }
        psum += __shfl_xor_sync(0xffffffffu, psum, 1);
        psum += __shfl_xor_sync(0xffffffffu, psum, 2);
        l_run += psum;
        m_run = m_new;
        __syncwarp();

        // --- O += P V for this thread's 16 strided output dims ---
#pragma unroll 8
        for (int k = 0; k < 64; k++) {
            float p = Ss[r * LDT + k];
#pragma unroll
            for (int i = 0; i < 16; i++) {
                int d = lane4 + 4 * i;
                o[i] += p * Vs[k * LDT + d];
            }
        }
    }

    // --- epilogue: normalize, write [B,T,C] layout ---
    float inv_l = 1.0f / l_run;
    float* obase = out + ((size_t)b * TT + it * 64 + r) * CC + h * HD;
#pragma unroll
    for (int i = 0; i < 16; i++) {
        obase[lane4 + 4 * i] = o[i] * inv_l;
    }
}

// ---------------------------------------------------------------------------
extern "C" void kernel_launch(void* const* d_in, const int* in_sizes, int n_in,
                              void* d_out, int out_size)
{
    const float* x     = (const float*)d_in[0];
    const float* Wqkv  = (const float*)d_in[1];
    const float* bqkv  = (const float*)d_in[2];
    const float* Wproj = (const float*)d_in[3];
    const float* bproj = (const float*)d_in[4];
    float* out = (float*)d_out;

    float *qkv, *att;
    cudaGetSymbolAddress((void**)&qkv, g_qkv);
    cudaGetSymbolAddress((void**)&att, g_att);

    cudaFuncSetAttribute(attn_kernel,
                         cudaFuncAttributeMaxDynamicSharedMemorySize, ATTN_SMEM);

    dim3 blk(256);
    // 1) qkv = x @ W_qkv + b_qkv   [8192,1024]x[1024,3072]
    sgemm_bias<<<dim3(3 * CC / 128, BT / 128), blk>>>(x, Wqkv, bqkv, qkv, BT, 3 * CC, CC);
    // 2) attention
    attn_kernel<<<dim3(TT / 64, HH, BB), blk, ATTN_SMEM>>>(qkv, att);
    // 3) out = att @ W_proj + b_proj   [8192,1024]x[1024,1024]
    sgemm_bias<<<dim3(CC / 128, BT / 128), blk>>>(att, Wproj, bproj, out, BT, CC, CC);
}

// round 3
// speedup vs baseline: 1.2971x; 1.2971x over previous
#include <cuda_runtime.h>
#include <cuda_bf16.h>
#include <cstdint>
#include <math.h>

// Problem constants
#define BB 4
#define TT 2048
#define CC 1024
#define HH 16
#define HD 64
#define BT (BB*TT)          // 8192

// Scratch (device globals: allocation-free per harness rules)
__device__ float g_qkv[(size_t)BT * 3 * CC];   // [B*T, 3C]
__device__ float g_att[(size_t)BT * CC];       // [B*T, C]

// ===========================================================================
// Helpers
// ===========================================================================
__device__ __forceinline__ uint32_t smem_u32(const void* p) {
    uint32_t a;
    asm("{ .reg .u64 t; cvta.to.shared.u64 t, %1; cvt.u32.u64 %0, t; }"
        : "=r"(a) : "l"(p));
    return a;
}

#define LDSM_X4(r, addr) \
    asm volatile("ldmatrix.sync.aligned.m8n8.x4.shared.b16 {%0,%1,%2,%3}, [%4];" \
        : "=r"((r)[0]), "=r"((r)[1]), "=r"((r)[2]), "=r"((r)[3]) : "r"(addr))

#define LDSM_X2T(r, addr) \
    asm volatile("ldmatrix.sync.aligned.m8n8.x2.trans.shared.b16 {%0,%1}, [%2];" \
        : "=r"((r)[0]), "=r"((r)[1]) : "r"(addr))

#define MMA_BF16(c, a, b) \
    asm volatile("mma.sync.aligned.m16n8k16.row.col.f32.bf16.bf16.f32 " \
        "{%0,%1,%2,%3}, {%4,%5,%6,%7}, {%8,%9}, {%0,%1,%2,%3};" \
        : "+f"((c)[0]), "+f"((c)[1]), "+f"((c)[2]), "+f"((c)[3]) \
        : "r"((a)[0]), "r"((a)[1]), "r"((a)[2]), "r"((a)[3]), \
          "r"((b)[0]), "r"((b)[1]))

__device__ __forceinline__ uint32_t pack_bf16(float a, float b) {
    __nv_bfloat162 t = __floats2bfloat162_rn(a, b);
    return *(uint32_t*)&t;
}

// ===========================================================================
// HMMA split-bf16 GEMM with bias: C[M,N] = A[M,K] @ B[K,N] + bias[N]
// 128x128 tile, BK=64. 8 warps (2x4), warp tile 64x32, m16n8k16 frags.
// Accumulates Ahi*Bhi + Ahi*Blo + Alo*Bhi in fp32 (residual ~2^-16).
// Requires M%128==0, N%128==0, K%64==0.
// ===========================================================================
#define AS_STRIDE 72          // bf16 elems per row (64 + 8 pad): 36 words, 4k bank pattern
#define BS_STRIDE 136         // bf16 elems per row (128 + 8 pad): 68 words, 4k bank pattern
#define AS_BYTES (128 * AS_STRIDE * 2)   // 18432
#define BS_BYTES (64 * BS_STRIDE * 2)    // 17408
#define GEMM_SMEM (2 * AS_BYTES + 2 * BS_BYTES)  // 71680

__global__ __launch_bounds__(256) void gemm_hmma(
    const float* __restrict__ A, const float* __restrict__ B,
    const float* __restrict__ bias, float* __restrict__ C,
    int M, int N, int K)
{
    extern __shared__ char sm[];
    __nv_bfloat16* AsH = (__nv_bfloat16*)(sm);
    __nv_bfloat16* AsL = (__nv_bfloat16*)(sm + AS_BYTES);
    __nv_bfloat16* BsH = (__nv_bfloat16*)(sm + 2 * AS_BYTES);
    __nv_bfloat16* BsL = (__nv_bfloat16*)(sm + 2 * AS_BYTES + BS_BYTES);

    const int tid  = threadIdx.x;
    const int lane = tid & 31;
    const int wid  = tid >> 5;
    const int wm   = wid >> 2;        // 0..1
    const int wn   = wid & 3;         // 0..3
    const int rowBase = blockIdx.y * 128;
    const int colBase = blockIdx.x * 128;

    const uint32_t asH = smem_u32(AsH);
    const uint32_t asL = smem_u32(AsL);
    const uint32_t bsH = smem_u32(BsH);
    const uint32_t bsL = smem_u32(BsL);

    float acc[4][4][4] = {};

    const int NS = K >> 6;
    for (int s = 0; s < NS; s++) {
        __syncthreads();
        const int k0 = s << 6;

        // ---- A: 128 rows x 64 k fp32 -> hi/lo bf16 at [m][k], stride 72 ----
#pragma unroll
        for (int i = 0; i < 8; i++) {
            int idx = tid + i * 256;
            int m  = idx >> 4;
            int k4 = (idx & 15) * 4;
            float4 v = *(const float4*)&A[(size_t)(rowBase + m) * K + k0 + k4];
            float hx = __bfloat162float(__float2bfloat16(v.x));
            float hy = __bfloat162float(__float2bfloat16(v.y));
            float hz = __bfloat162float(__float2bfloat16(v.z));
            float hw = __bfloat162float(__float2bfloat16(v.w));
            uint2 hu = { pack_bf16(hx, hy), pack_bf16(hz, hw) };
            uint2 lu = { pack_bf16(v.x - hx, v.y - hy), pack_bf16(v.z - hz, v.w - hw) };
            *(uint2*)&AsH[m * AS_STRIDE + k4] = hu;
            *(uint2*)&AsL[m * AS_STRIDE + k4] = lu;
        }

        // ---- B: 64 k x 128 n fp32 -> hi/lo bf16 at [k][n], stride 136 ----
#pragma unroll
        for (int i = 0; i < 8; i++) {
            int idx = tid + i * 256;
            int k  = idx >> 5;
            int n4 = (idx & 31) * 4;
            float4 v = *(const float4*)&B[(size_t)(k0 + k) * N + colBase + n4];
            float hx = __bfloat162float(__float2bfloat16(v.x));
            float hy = __bfloat162float(__float2bfloat16(v.y));
            float hz = __bfloat162float(__float2bfloat16(v.z));
            float hw = __bfloat162float(__float2bfloat16(v.w));
            uint2 hu = { pack_bf16(hx, hy), pack_bf16(hz, hw) };
            uint2 lu = { pack_bf16(v.x - hx, v.y - hy), pack_bf16(v.z - hz, v.w - hw) };
            *(uint2*)&BsH[k * BS_STRIDE + n4] = hu;
            *(uint2*)&BsL[k * BS_STRIDE + n4] = lu;
        }
        __syncthreads();

        // ---- MMA over 4 k16 steps ----
#pragma unroll
        for (int ks = 0; ks < 4; ks++) {
            uint32_t aH[4][4], aL[4][4];
#pragma unroll
            for (int mf = 0; mf < 4; mf++) {
                uint32_t off = ((wm * 64 + mf * 16 + (lane & 15)) * AS_STRIDE
                                + ks * 16 + (lane >> 4) * 8) * 2;
                LDSM_X4(aH[mf], asH + off);
                LDSM_X4(aL[mf], asL + off);
            }
#pragma unroll
            for (int nf = 0; nf < 4; nf++) {
                uint32_t bH[2], bL[2];
                uint32_t off = ((ks * 16 + (lane & 15)) * BS_STRIDE
                                + wn * 32 + nf * 8) * 2;
                LDSM_X2T(bH, bsH + off);
                LDSM_X2T(bL, bsL + off);
#pragma unroll
                for (int mf = 0; mf < 4; mf++) {
                    MMA_BF16(acc[mf][nf], aH[mf], bH);
                    MMA_BF16(acc[mf][nf], aH[mf], bL);
                    MMA_BF16(acc[mf][nf], aL[mf], bH);
                }
            }
        }
    }

    // ---- Epilogue: direct global stores with bias ----
#pragma unroll
    for (int nf = 0; nf < 4; nf++) {
        int c = colBase + wn * 32 + nf * 8 + 2 * (lane & 3);
        float2 bv = *(const float2*)&bias[c];
#pragma unroll
        for (int mf = 0; mf < 4; mf++) {
            int r0 = rowBase + wm * 64 + mf * 16 + (lane >> 2);
            float2 o0 = { acc[mf][nf][0] + bv.x, acc[mf][nf][1] + bv.y };
            float2 o1 = { acc[mf][nf][2] + bv.x, acc[mf][nf][3] + bv.y };
            *(float2*)&C[(size_t)r0 * N + c] = o0;
            *(float2*)&C[(size_t)(r0 + 8) * N + c] = o1;
        }
    }
}

// ---------------------------------------------------------------------------
// Causal flash attention (unchanged from round 1; passing at rel_err 1.2e-6).
// Grid: (T/64, H, B). Block: 256 threads = 64 rows x 4 threads/row.
// ---------------------------------------------------------------------------
#define LDT 68
#define ATTN_SMEM (4 * 64 * LDT * (int)sizeof(float))

__global__ __launch_bounds__(256) void attn_kernel(
    const float* __restrict__ qkv, float* __restrict__ out)
{
    extern __shared__ float smf[];
    float* Qs = smf;
    float* Ks = smf + 64 * LDT;
    float* Vs = smf + 2 * 64 * LDT;
    float* Ss = smf + 3 * 64 * LDT;

    const int it = blockIdx.x;
    const int h  = blockIdx.y;
    const int b  = blockIdx.z;
    const int tid = threadIdx.x;

    const size_t rowStride = 3 * CC;
    const float* qbase = qkv + (size_t)b * TT * rowStride + (size_t)h * HD;
    const float* kbase = qbase + CC;
    const float* vbase = qbase + 2 * CC;

#pragma unroll
    for (int i = 0; i < 4; i++) {
        int idx = tid + i * 256;
        int row = idx >> 4;
        int v4  = (idx & 15) * 4;
        float4 qv = *(const float4*)&qbase[(size_t)(it * 64 + row) * rowStride + v4];
        *(float4*)&Qs[row * LDT + v4] = qv;
    }

    const int r     = tid >> 2;
    const int lane4 = tid & 3;

    float o[16];
#pragma unroll
    for (int i = 0; i < 16; i++) o[i] = 0.0f;
    float m_run = -1e30f;
    float l_run = 0.0f;
    const float scale = 0.125f;

    for (int jt = 0; jt <= it; jt++) {
        __syncthreads();
#pragma unroll
        for (int i = 0; i < 4; i++) {
            int idx = tid + i * 256;
            int row = idx >> 4;
            int v4  = (idx & 15) * 4;
            size_t goff = (size_t)(jt * 64 + row) * rowStride + v4;
            *(float4*)&Ks[row * LDT + v4] = *(const float4*)&kbase[goff];
            *(float4*)&Vs[row * LDT + v4] = *(const float4*)&vbase[goff];
        }
        __syncthreads();

        float s[16];
#pragma unroll
        for (int i = 0; i < 16; i++) s[i] = 0.0f;
#pragma unroll 8
        for (int d = 0; d < 64; d++) {
            float qd = Qs[r * LDT + d];
#pragma unroll
            for (int i = 0; i < 16; i++) {
                int c = lane4 + 4 * i;
                s[i] += qd * Ks[c * LDT + d];
            }
        }

        if (jt == it) {
#pragma unroll
            for (int i = 0; i < 16; i++) {
                int c = lane4 + 4 * i;
                s[i] = (c > r) ? -1e30f : s[i] * scale;
            }
        } else {
#pragma unroll
            for (int i = 0; i < 16; i++) s[i] *= scale;
        }

        float mloc = -1e30f;
#pragma unroll
        for (int i = 0; i < 16; i++) mloc = fmaxf(mloc, s[i]);
        mloc = fmaxf(mloc, __shfl_xor_sync(0xffffffffu, mloc, 1));
        mloc = fmaxf(mloc, __shfl_xor_sync(0xffffffffu, mloc, 2));
        float m_new = fmaxf(m_run, mloc);
        float corr = __expf(m_run - m_new);
        l_run *= corr;
#pragma unroll
        for (int i = 0; i < 16; i++) o[i] *= corr;

        float psum = 0.0f;
#pragma unroll
        for (int i = 0; i < 16; i++) {
            float p = __expf(s[i] - m_new);
            psum += p;
            Ss[r * LDT + lane4 + 4 * i] = p;
        }
        psum += __shfl_xor_sync(0xffffffffu, psum, 1);
        psum += __shfl_xor_sync(0xffffffffu, psum, 2);
        l_run += psum;
        m_run = m_new;
        __syncwarp();

#pragma unroll 8
        for (int k = 0; k < 64; k++) {
            float p = Ss[r * LDT + k];
#pragma unroll
            for (int i = 0; i < 16; i++) {
                int d = lane4 + 4 * i;
                o[i] += p * Vs[k * LDT + d];
            }
        }
    }

    float inv_l = 1.0f / l_run;
    float* obase = out + ((size_t)b * TT + it * 64 + r) * CC + h * HD;
#pragma unroll
    for (int i = 0; i < 16; i++) {
        obase[lane4 + 4 * i] = o[i] * inv_l;
    }
}

// ---------------------------------------------------------------------------
extern "C" void kernel_launch(void* const* d_in, const int* in_sizes, int n_in,
                              void* d_out, int out_size)
{
    const float* x     = (const float*)d_in[0];
    const float* Wqkv  = (const float*)d_in[1];
    const float* bqkv  = (const float*)d_in[2];
    const float* Wproj = (const float*)d_in[3];
    const float* bproj = (const float*)d_in[4];
    float* out = (float*)d_out;

    float *qkv, *att;
    cudaGetSymbolAddress((void**)&qkv, g_qkv);
    cudaGetSymbolAddress((void**)&att, g_att);

    cudaFuncSetAttribute(gemm_hmma,
                         cudaFuncAttributeMaxDynamicSharedMemorySize, GEMM_SMEM);
    cudaFuncSetAttribute(attn_kernel,
                         cudaFuncAttributeMaxDynamicSharedMemorySize, ATTN_SMEM);

    dim3 blk(256);
    // 1) qkv = x @ W_qkv + b_qkv   [8192,1024]x[1024,3072]
    gemm_hmma<<<dim3(3 * CC / 128, BT / 128), blk, GEMM_SMEM>>>(x, Wqkv, bqkv, qkv, BT, 3 * CC, CC);
    // 2) attention
    attn_kernel<<<dim3(TT / 64, HH, BB), blk, ATTN_SMEM>>>(qkv, att);
    // 3) out = att @ W_proj + b_proj   [8192,1024]x[1024,1024]
    gemm_hmma<<<dim3(CC / 128, BT / 128), blk, GEMM_SMEM>>>(att, Wproj, bproj, out, BT, CC, CC);
}

// round 4
// speedup vs baseline: 2.9942x; 2.3083x over previous
#include <cuda_runtime.h>
#include <cuda_bf16.h>
#include <cstdint>
#include <math.h>

// Problem constants
#define BB 4
#define TT 2048
#define CC 1024
#define HH 16
#define HD 64
#define BT (BB*TT)          // 8192

// Scratch (device globals: allocation-free per harness rules)
__device__ float g_qkv[(size_t)BT * 3 * CC];   // [B*T, 3C]
__device__ float g_att[(size_t)BT * CC];       // [B*T, C]

// ===========================================================================
// Helpers
// ===========================================================================
__device__ __forceinline__ uint32_t smem_u32(const void* p) {
    uint32_t a;
    asm("{ .reg .u64 t; cvta.to.shared.u64 t, %1; cvt.u32.u64 %0, t; }"
        : "=r"(a) : "l"(p));
    return a;
}

#define LDSM_X4(r, addr) \
    asm volatile("ldmatrix.sync.aligned.m8n8.x4.shared.b16 {%0,%1,%2,%3}, [%4];" \
        : "=r"((r)[0]), "=r"((r)[1]), "=r"((r)[2]), "=r"((r)[3]) : "r"(addr))

#define LDSM_X2T(r, addr) \
    asm volatile("ldmatrix.sync.aligned.m8n8.x2.trans.shared.b16 {%0,%1}, [%2];" \
        : "=r"((r)[0]), "=r"((r)[1]) : "r"(addr))

#define LDSM_X4T(r, addr) \
    asm volatile("ldmatrix.sync.aligned.m8n8.x4.trans.shared.b16 {%0,%1,%2,%3}, [%4];" \
        : "=r"((r)[0]), "=r"((r)[1]), "=r"((r)[2]), "=r"((r)[3]) : "r"(addr))

#define MMA_BF16(c, a, b) \
    asm volatile("mma.sync.aligned.m16n8k16.row.col.f32.bf16.bf16.f32 " \
        "{%0,%1,%2,%3}, {%4,%5,%6,%7}, {%8,%9}, {%0,%1,%2,%3};" \
        : "+f"((c)[0]), "+f"((c)[1]), "+f"((c)[2]), "+f"((c)[3]) \
        : "r"((a)[0]), "r"((a)[1]), "r"((a)[2]), "r"((a)[3]), \
          "r"((b)[0]), "r"((b)[1]))

__device__ __forceinline__ uint32_t pack_bf16(float a, float b) {
    __nv_bfloat162 t = __floats2bfloat162_rn(a, b);
    return *(uint32_t*)&t;
}

// split x into hi (bf16-representable float) and lo = x - hi
__device__ __forceinline__ void split2(float a, float b, uint32_t& hi, uint32_t& lo) {
    float ha = __bfloat162float(__float2bfloat16(a));
    float hb = __bfloat162float(__float2bfloat16(b));
    hi = pack_bf16(ha, hb);
    lo = pack_bf16(a - ha, b - hb);
}

// ===========================================================================
// HMMA split-bf16 GEMM with bias (unchanged from round 3; passing)
// ===========================================================================
#define AS_STRIDE 72
#define BS_STRIDE 136
#define AS_BYTES (128 * AS_STRIDE * 2)
#define BS_BYTES (64 * BS_STRIDE * 2)
#define GEMM_SMEM (2 * AS_BYTES + 2 * BS_BYTES)

__global__ __launch_bounds__(256) void gemm_hmma(
    const float* __restrict__ A, const float* __restrict__ B,
    const float* __restrict__ bias, float* __restrict__ C,
    int M, int N, int K)
{
    extern __shared__ char sm[];
    __nv_bfloat16* AsH = (__nv_bfloat16*)(sm);
    __nv_bfloat16* AsL = (__nv_bfloat16*)(sm + AS_BYTES);
    __nv_bfloat16* BsH = (__nv_bfloat16*)(sm + 2 * AS_BYTES);
    __nv_bfloat16* BsL = (__nv_bfloat16*)(sm + 2 * AS_BYTES + BS_BYTES);

    const int tid  = threadIdx.x;
    const int lane = tid & 31;
    const int wid  = tid >> 5;
    const int wm   = wid >> 2;
    const int wn   = wid & 3;
    const int rowBase = blockIdx.y * 128;
    const int colBase = blockIdx.x * 128;

    const uint32_t asH = smem_u32(AsH);
    const uint32_t asL = smem_u32(AsL);
    const uint32_t bsH = smem_u32(BsH);
    const uint32_t bsL = smem_u32(BsL);

    float acc[4][4][4] = {};

    const int NS = K >> 6;
    for (int s = 0; s < NS; s++) {
        __syncthreads();
        const int k0 = s << 6;

#pragma unroll
        for (int i = 0; i < 8; i++) {
            int idx = tid + i * 256;
            int m  = idx >> 4;
            int k4 = (idx & 15) * 4;
            float4 v = *(const float4*)&A[(size_t)(rowBase + m) * K + k0 + k4];
            uint32_t h0, l0, h1, l1;
            split2(v.x, v.y, h0, l0);
            split2(v.z, v.w, h1, l1);
            uint2 hu = { h0, h1 }, lu = { l0, l1 };
            *(uint2*)&AsH[m * AS_STRIDE + k4] = hu;
            *(uint2*)&AsL[m * AS_STRIDE + k4] = lu;
        }

#pragma unroll
        for (int i = 0; i < 8; i++) {
            int idx = tid + i * 256;
            int k  = idx >> 5;
            int n4 = (idx & 31) * 4;
            float4 v = *(const float4*)&B[(size_t)(k0 + k) * N + colBase + n4];
            uint32_t h0, l0, h1, l1;
            split2(v.x, v.y, h0, l0);
            split2(v.z, v.w, h1, l1);
            uint2 hu = { h0, h1 }, lu = { l0, l1 };
            *(uint2*)&BsH[k * BS_STRIDE + n4] = hu;
            *(uint2*)&BsL[k * BS_STRIDE + n4] = lu;
        }
        __syncthreads();

#pragma unroll
        for (int ks = 0; ks < 4; ks++) {
            uint32_t aH[4][4], aL[4][4];
#pragma unroll
            for (int mf = 0; mf < 4; mf++) {
                uint32_t off = ((wm * 64 + mf * 16 + (lane & 15)) * AS_STRIDE
                                + ks * 16 + (lane >> 4) * 8) * 2;
                LDSM_X4(aH[mf], asH + off);
                LDSM_X4(aL[mf], asL + off);
            }
#pragma unroll
            for (int nf = 0; nf < 4; nf++) {
                uint32_t bH[2], bL[2];
                uint32_t off = ((ks * 16 + (lane & 15)) * BS_STRIDE
                                + wn * 32 + nf * 8) * 2;
                LDSM_X2T(bH, bsH + off);
                LDSM_X2T(bL, bsL + off);
#pragma unroll
                for (int mf = 0; mf < 4; mf++) {
                    MMA_BF16(acc[mf][nf], aH[mf], bH);
                    MMA_BF16(acc[mf][nf], aH[mf], bL);
                    MMA_BF16(acc[mf][nf], aL[mf], bH);
                }
            }
        }
    }

#pragma unroll
    for (int nf = 0; nf < 4; nf++) {
        int c = colBase + wn * 32 + nf * 8 + 2 * (lane & 3);
        float2 bv = *(const float2*)&bias[c];
#pragma unroll
        for (int mf = 0; mf < 4; mf++) {
            int r0 = rowBase + wm * 64 + mf * 16 + (lane >> 2);
            float2 o0 = { acc[mf][nf][0] + bv.x, acc[mf][nf][1] + bv.y };
            float2 o1 = { acc[mf][nf][2] + bv.x, acc[mf][nf][3] + bv.y };
            *(float2*)&C[(size_t)r0 * N + c] = o0;
            *(float2*)&C[(size_t)(r0 + 8) * N + c] = o1;
        }
    }
}

// ===========================================================================
// HMMA flash attention (causal), split-bf16 (3-pass) for QK^T and PV.
// Grid: (T/128, H, B). Block: 256 threads = 8 warps x 16 q-rows.
// smem: Q hi/lo [128][64] str72; Kt hi/lo [64 dim][64 key] str72;
//       V hi/lo [64 key][64 dim] str72.
// ===========================================================================
#define QS 72
#define Q_BYTES  (128 * QS * 2)      // 18432
#define KV_BYTES (64 * QS * 2)       // 9216
#define ATTN_SMEM (2 * Q_BYTES + 4 * KV_BYTES)   // 73728

__global__ __launch_bounds__(256) void attn_hmma(
    const float* __restrict__ qkv, float* __restrict__ out)
{
    extern __shared__ char sm[];
    __nv_bfloat16* Qhi  = (__nv_bfloat16*)(sm);
    __nv_bfloat16* Qlo  = (__nv_bfloat16*)(sm + Q_BYTES);
    __nv_bfloat16* Kthi = (__nv_bfloat16*)(sm + 2 * Q_BYTES);
    __nv_bfloat16* Ktlo = (__nv_bfloat16*)(sm + 2 * Q_BYTES + KV_BYTES);
    __nv_bfloat16* Vhi  = (__nv_bfloat16*)(sm + 2 * Q_BYTES + 2 * KV_BYTES);
    __nv_bfloat16* Vlo  = (__nv_bfloat16*)(sm + 2 * Q_BYTES + 3 * KV_BYTES);

    const int tid  = threadIdx.x;
    const int lane = tid & 31;
    const int w    = tid >> 5;
    const int qt = blockIdx.x;
    const int h  = blockIdx.y;
    const int b  = blockIdx.z;
    const int qb = qt * 128;

    const size_t rs = 3 * CC;
    const float* qp0 = qkv + (size_t)b * TT * rs + (size_t)h * HD;

    // ---- load Q tile (128 x 64), split hi/lo ----
#pragma unroll
    for (int i = 0; i < 8; i++) {
        int idx = tid + i * 256;
        int m  = idx >> 4;
        int d4 = (idx & 15) * 4;
        float4 v = *(const float4*)&qp0[(size_t)(qb + m) * rs + d4];
        uint32_t h0, l0, h1, l1;
        split2(v.x, v.y, h0, l0);
        split2(v.z, v.w, h1, l1);
        uint2 hu = { h0, h1 }, lu = { l0, l1 };
        *(uint2*)&Qhi[m * QS + d4] = hu;
        *(uint2*)&Qlo[m * QS + d4] = lu;
    }

    const uint32_t qhiA  = smem_u32(Qhi),  qloA  = smem_u32(Qlo);
    const uint32_t kthiA = smem_u32(Kthi), ktloA = smem_u32(Ktlo);
    const uint32_t vhiA  = smem_u32(Vhi),  vloA  = smem_u32(Vlo);

    float S[8][4];
    float O[8][4] = {};
    float m_run[2] = { -1e30f, -1e30f };
    float l_run[2] = { 0.0f, 0.0f };
    const float scale = 0.125f;

    const int wmin = qb + w * 16;
    const int r_in = lane >> 2;
    const int c2   = (lane & 3) * 2;
    const int row0 = wmin + r_in;
    const int row1 = row0 + 8;

    const int n_tiles = 2 * qt + 2;
    for (int jt = 0; jt < n_tiles; jt++) {
        const int kvb = jt * 64;
        __syncthreads();

        // ---- load K (transposed into [dim][key]) and V ([key][dim]) ----
        const float* kp = qkv + ((size_t)b * TT + kvb) * rs + CC + h * HD;
        const float* vp = kp + CC;
#pragma unroll
        for (int i = 0; i < 4; i++) {
            int idx = tid + i * 256;
            int key = idx >> 4;
            int d4  = (idx & 15) * 4;
            float4 kv4 = *(const float4*)&kp[(size_t)key * rs + d4];
            float ke[4] = { kv4.x, kv4.y, kv4.z, kv4.w };
#pragma unroll
            for (int e = 0; e < 4; e++) {
                float hh = __bfloat162float(__float2bfloat16(ke[e]));
                Kthi[(d4 + e) * QS + key] = __float2bfloat16(hh);
                Ktlo[(d4 + e) * QS + key] = __float2bfloat16(ke[e] - hh);
            }
            float4 vv4 = *(const float4*)&vp[(size_t)key * rs + d4];
            uint32_t h0, l0, h1, l1;
            split2(vv4.x, vv4.y, h0, l0);
            split2(vv4.z, vv4.w, h1, l1);
            uint2 hu = { h0, h1 }, lu = { l0, l1 };
            *(uint2*)&Vhi[key * QS + d4] = hu;
            *(uint2*)&Vlo[key * QS + d4] = lu;
        }
        __syncthreads();

        if (kvb > wmin + 15) continue;   // warp-uniform: tile fully masked for this warp

        // ---- S = Q K^T (3-pass split) ----
#pragma unroll
        for (int nf = 0; nf < 8; nf++)
#pragma unroll
            for (int e = 0; e < 4; e++) S[nf][e] = 0.0f;

#pragma unroll
        for (int ks = 0; ks < 4; ks++) {
            uint32_t qh[4], ql[4];
            uint32_t qoff = ((w * 16 + (lane & 15)) * QS + ks * 16 + (lane >> 4) * 8) * 2;
            LDSM_X4(qh, qhiA + qoff);
            LDSM_X4(ql, qloA + qoff);
#pragma unroll
            for (int np = 0; np < 4; np++) {
                uint32_t kh[4], kl[4];
                uint32_t koff = ((ks * 16 + (lane & 15)) * QS + np * 16 + (lane >> 4) * 8) * 2;
                LDSM_X4T(kh, kthiA + koff);
                LDSM_X4T(kl, ktloA + koff);
                MMA_BF16(S[2*np],   qh, kh);
                MMA_BF16(S[2*np],   qh, kl);
                MMA_BF16(S[2*np],   ql, kh);
                MMA_BF16(S[2*np+1], qh, kh + 2);
                MMA_BF16(S[2*np+1], qh, kl + 2);
                MMA_BF16(S[2*np+1], ql, kh + 2);
            }
        }

        // ---- scale + causal mask + row max ----
        const bool full = (kvb + 63 <= wmin);
        float mx0 = -1e30f, mx1 = -1e30f;
#pragma unroll
        for (int nf = 0; nf < 8; nf++) {
            int col = kvb + nf * 8 + c2;
            float s0 = S[nf][0] * scale;
            float s1 = S[nf][1] * scale;
            float s2 = S[nf][2] * scale;
            float s3 = S[nf][3] * scale;
            if (!full) {
                if (col     > row0) s0 = -1e30f;
                if (col + 1 > row0) s1 = -1e30f;
                if (col     > row1) s2 = -1e30f;
                if (col + 1 > row1) s3 = -1e30f;
            }
            S[nf][0] = s0; S[nf][1] = s1; S[nf][2] = s2; S[nf][3] = s3;
            mx0 = fmaxf(mx0, fmaxf(s0, s1));
            mx1 = fmaxf(mx1, fmaxf(s2, s3));
        }
        mx0 = fmaxf(mx0, __shfl_xor_sync(0xffffffffu, mx0, 1));
        mx0 = fmaxf(mx0, __shfl_xor_sync(0xffffffffu, mx0, 2));
        mx1 = fmaxf(mx1, __shfl_xor_sync(0xffffffffu, mx1, 1));
        mx1 = fmaxf(mx1, __shfl_xor_sync(0xffffffffu, mx1, 2));

        float mn0 = fmaxf(m_run[0], mx0);
        float mn1 = fmaxf(m_run[1], mx1);
        float corr0 = __expf(m_run[0] - mn0);
        float corr1 = __expf(m_run[1] - mn1);
        l_run[0] *= corr0;
        l_run[1] *= corr1;
#pragma unroll
        for (int nf = 0; nf < 8; nf++) {
            O[nf][0] *= corr0; O[nf][1] *= corr0;
            O[nf][2] *= corr1; O[nf][3] *= corr1;
        }

        float sum0 = 0.0f, sum1 = 0.0f;
#pragma unroll
        for (int nf = 0; nf < 8; nf++) {
            float p0 = __expf(S[nf][0] - mn0);
            float p1 = __expf(S[nf][1] - mn0);
            float p2 = __expf(S[nf][2] - mn1);
            float p3 = __expf(S[nf][3] - mn1);
            S[nf][0] = p0; S[nf][1] = p1; S[nf][2] = p2; S[nf][3] = p3;
            sum0 += p0 + p1;
            sum1 += p2 + p3;
        }
        sum0 += __shfl_xor_sync(0xffffffffu, sum0, 1);
        sum0 += __shfl_xor_sync(0xffffffffu, sum0, 2);
        sum1 += __shfl_xor_sync(0xffffffffu, sum1, 1);
        sum1 += __shfl_xor_sync(0xffffffffu, sum1, 2);
        l_run[0] += sum0;
        l_run[1] += sum1;
        m_run[0] = mn0;
        m_run[1] = mn1;

        // ---- O += P V (3-pass split); S frags reinterpret as A frags ----
#pragma unroll
        for (int j = 0; j < 4; j++) {
            uint32_t aH[4], aL[4];
            split2(S[2*j][0],   S[2*j][1],   aH[0], aL[0]);
            split2(S[2*j][2],   S[2*j][3],   aH[1], aL[1]);
            split2(S[2*j+1][0], S[2*j+1][1], aH[2], aL[2]);
            split2(S[2*j+1][2], S[2*j+1][3], aH[3], aL[3]);
#pragma unroll
            for (int np = 0; np < 4; np++) {
                uint32_t vh[4], vl[4];
                uint32_t voff = ((j * 16 + (lane & 15)) * QS + np * 16 + (lane >> 4) * 8) * 2;
                LDSM_X4T(vh, vhiA + voff);
                LDSM_X4T(vl, vloA + voff);
                MMA_BF16(O[2*np],   aH, vh);
                MMA_BF16(O[2*np],   aH, vl);
                MMA_BF16(O[2*np],   aL, vh);
                MMA_BF16(O[2*np+1], aH, vh + 2);
                MMA_BF16(O[2*np+1], aH, vl + 2);
                MMA_BF16(O[2*np+1], aL, vh + 2);
            }
        }
    }

    // ---- epilogue: normalize, write [B,T,C] ----
    float inv0 = 1.0f / l_run[0];
    float inv1 = 1.0f / l_run[1];
    float* o0 = out + ((size_t)b * TT + row0) * CC + h * HD;
    float* o1 = out + ((size_t)b * TT + row1) * CC + h * HD;
#pragma unroll
    for (int nf = 0; nf < 8; nf++) {
        int c = nf * 8 + c2;
        float2 a = { O[nf][0] * inv0, O[nf][1] * inv0 };
        float2 d = { O[nf][2] * inv1, O[nf][3] * inv1 };
        *(float2*)&o0[c] = a;
        *(float2*)&o1[c] = d;
    }
}

// ---------------------------------------------------------------------------
extern "C" void kernel_launch(void* const* d_in, const int* in_sizes, int n_in,
                              void* d_out, int out_size)
{
    const float* x     = (const float*)d_in[0];
    const float* Wqkv  = (const float*)d_in[1];
    const float* bqkv  = (const float*)d_in[2];
    const float* Wproj = (const float*)d_in[3];
    const float* bproj = (const float*)d_in[4];
    float* out = (float*)d_out;

    float *qkv, *att;
    cudaGetSymbolAddress((void**)&qkv, g_qkv);
    cudaGetSymbolAddress((void**)&att, g_att);

    cudaFuncSetAttribute(gemm_hmma,
                         cudaFuncAttributeMaxDynamicSharedMemorySize, GEMM_SMEM);
    cudaFuncSetAttribute(attn_hmma,
                         cudaFuncAttributeMaxDynamicSharedMemorySize, ATTN_SMEM);

    dim3 blk(256);
    // 1) qkv = x @ W_qkv + b_qkv
    gemm_hmma<<<dim3(3 * CC / 128, BT / 128), blk, GEMM_SMEM>>>(x, Wqkv, bqkv, qkv, BT, 3 * CC, CC);
    // 2) attention
    attn_hmma<<<dim3(TT / 128, HH, BB), blk, ATTN_SMEM>>>(qkv, att);
    // 3) out = att @ W_proj + b_proj
    gemm_hmma<<<dim3(CC / 128, BT / 128), blk, GEMM_SMEM>>>(att, Wproj, bproj, out, BT, CC, CC);
}

// round 5
// speedup vs baseline: 3.5163x; 1.1744x over previous
#include <cuda_runtime.h>
#include <cuda_bf16.h>
#include <cstdint>
#include <math.h>

// Problem constants
#define BB 4
#define TT 2048
#define CC 1024
#define HH 16
#define HD 64
#define BT (BB*TT)          // 8192

// Scratch (device globals: allocation-free per harness rules)
__device__ float g_qkv[(size_t)BT * 3 * CC];   // [B*T, 3C]
__device__ float g_att[(size_t)BT * CC];       // [B*T, C]

// ===========================================================================
// Helpers
// ===========================================================================
__device__ __forceinline__ uint32_t smem_u32(const void* p) {
    uint32_t a;
    asm("{ .reg .u64 t; cvta.to.shared.u64 t, %1; cvt.u32.u64 %0, t; }"
        : "=r"(a) : "l"(p));
    return a;
}

#define LDSM_X4(r, addr) \
    asm volatile("ldmatrix.sync.aligned.m8n8.x4.shared.b16 {%0,%1,%2,%3}, [%4];" \
        : "=r"((r)[0]), "=r"((r)[1]), "=r"((r)[2]), "=r"((r)[3]) : "r"(addr))

#define LDSM_X2T(r, addr) \
    asm volatile("ldmatrix.sync.aligned.m8n8.x2.trans.shared.b16 {%0,%1}, [%2];" \
        : "=r"((r)[0]), "=r"((r)[1]) : "r"(addr))

#define LDSM_X4T(r, addr) \
    asm volatile("ldmatrix.sync.aligned.m8n8.x4.trans.shared.b16 {%0,%1,%2,%3}, [%4];" \
        : "=r"((r)[0]), "=r"((r)[1]), "=r"((r)[2]), "=r"((r)[3]) : "r"(addr))

#define MMA_BF16(c, a, b) \
    asm volatile("mma.sync.aligned.m16n8k16.row.col.f32.bf16.bf16.f32 " \
        "{%0,%1,%2,%3}, {%4,%5,%6,%7}, {%8,%9}, {%0,%1,%2,%3};" \
        : "+f"((c)[0]), "+f"((c)[1]), "+f"((c)[2]), "+f"((c)[3]) \
        : "r"((a)[0]), "r"((a)[1]), "r"((a)[2]), "r"((a)[3]), \
          "r"((b)[0]), "r"((b)[1]))

__device__ __forceinline__ uint32_t pack_bf16(float a, float b) {
    __nv_bfloat162 t = __floats2bfloat162_rn(a, b);
    return *(uint32_t*)&t;
}

// split x into hi (bf16-representable float) and lo = x - hi
__device__ __forceinline__ void split2(float a, float b, uint32_t& hi, uint32_t& lo) {
    float ha = __bfloat162float(__float2bfloat16(a));
    float hb = __bfloat162float(__float2bfloat16(b));
    hi = pack_bf16(ha, hb);
    lo = pack_bf16(a - ha, b - hb);
}

// ===========================================================================
// HMMA split-bf16 GEMM with bias: C[M,N] = A[M,K] @ B[K,N] + bias[N]
// 128x128 tile, BK=64. 8 warps (2x4), warp tile 64x32, m16n8k16 frags.
// Accumulates Ahi*Bhi + Ahi*Blo + Alo*Bhi in fp32 (residual ~2^-16).
// __launch_bounds__(256, 2): cap regs at 128 so 2 CTAs/SM co-reside and
// one CTA's load/convert phase overlaps the other's MMA phase.
// ===========================================================================
#define AS_STRIDE 72
#define BS_STRIDE 136
#define AS_BYTES (128 * AS_STRIDE * 2)
#define BS_BYTES (64 * BS_STRIDE * 2)
#define GEMM_SMEM (2 * AS_BYTES + 2 * BS_BYTES)

__global__ __launch_bounds__(256, 2) void gemm_hmma(
    const float* __restrict__ A, const float* __restrict__ B,
    const float* __restrict__ bias, float* __restrict__ C,
    int M, int N, int K)
{
    extern __shared__ char sm[];
    __nv_bfloat16* AsH = (__nv_bfloat16*)(sm);
    __nv_bfloat16* AsL = (__nv_bfloat16*)(sm + AS_BYTES);
    __nv_bfloat16* BsH = (__nv_bfloat16*)(sm + 2 * AS_BYTES);
    __nv_bfloat16* BsL = (__nv_bfloat16*)(sm + 2 * AS_BYTES + BS_BYTES);

    const int tid  = threadIdx.x;
    const int lane = tid & 31;
    const int wid  = tid >> 5;
    const int wm   = wid >> 2;
    const int wn   = wid & 3;
    const int rowBase = blockIdx.y * 128;
    const int colBase = blockIdx.x * 128;

    const uint32_t asH = smem_u32(AsH);
    const uint32_t asL = smem_u32(AsL);
    const uint32_t bsH = smem_u32(BsH);
    const uint32_t bsL = smem_u32(BsL);

    float acc[4][4][4] = {};

    const int NS = K >> 6;
    for (int s = 0; s < NS; s++) {
        __syncthreads();
        const int k0 = s << 6;

#pragma unroll
        for (int i = 0; i < 8; i++) {
            int idx = tid + i * 256;
            int m  = idx >> 4;
            int k4 = (idx & 15) * 4;
            float4 v = *(const float4*)&A[(size_t)(rowBase + m) * K + k0 + k4];
            uint32_t h0, l0, h1, l1;
            split2(v.x, v.y, h0, l0);
            split2(v.z, v.w, h1, l1);
            uint2 hu = { h0, h1 }, lu = { l0, l1 };
            *(uint2*)&AsH[m * AS_STRIDE + k4] = hu;
            *(uint2*)&AsL[m * AS_STRIDE + k4] = lu;
        }

#pragma unroll
        for (int i = 0; i < 8; i++) {
            int idx = tid + i * 256;
            int k  = idx >> 5;
            int n4 = (idx & 31) * 4;
            float4 v = *(const float4*)&B[(size_t)(k0 + k) * N + colBase + n4];
            uint32_t h0, l0, h1, l1;
            split2(v.x, v.y, h0, l0);
            split2(v.z, v.w, h1, l1);
            uint2 hu = { h0, h1 }, lu = { l0, l1 };
            *(uint2*)&BsH[k * BS_STRIDE + n4] = hu;
            *(uint2*)&BsL[k * BS_STRIDE + n4] = lu;
        }
        __syncthreads();

#pragma unroll
        for (int ks = 0; ks < 4; ks++) {
            uint32_t aH[4][4], aL[4][4];
#pragma unroll
            for (int mf = 0; mf < 4; mf++) {
                uint32_t off = ((wm * 64 + mf * 16 + (lane & 15)) * AS_STRIDE
                                + ks * 16 + (lane >> 4) * 8) * 2;
                LDSM_X4(aH[mf], asH + off);
                LDSM_X4(aL[mf], asL + off);
            }
#pragma unroll
            for (int nf = 0; nf < 4; nf++) {
                uint32_t bH[2], bL[2];
                uint32_t off = ((ks * 16 + (lane & 15)) * BS_STRIDE
                                + wn * 32 + nf * 8) * 2;
                LDSM_X2T(bH, bsH + off);
                LDSM_X2T(bL, bsL + off);
#pragma unroll
                for (int mf = 0; mf < 4; mf++) {
                    MMA_BF16(acc[mf][nf], aH[mf], bH);
                    MMA_BF16(acc[mf][nf], aH[mf], bL);
                    MMA_BF16(acc[mf][nf], aL[mf], bH);
                }
            }
        }
    }

#pragma unroll
    for (int nf = 0; nf < 4; nf++) {
        int c = colBase + wn * 32 + nf * 8 + 2 * (lane & 3);
        float2 bv = *(const float2*)&bias[c];
#pragma unroll
        for (int mf = 0; mf < 4; mf++) {
            int r0 = rowBase + wm * 64 + mf * 16 + (lane >> 2);
            float2 o0 = { acc[mf][nf][0] + bv.x, acc[mf][nf][1] + bv.y };
            float2 o1 = { acc[mf][nf][2] + bv.x, acc[mf][nf][3] + bv.y };
            *(float2*)&C[(size_t)r0 * N + c] = o0;
            *(float2*)&C[(size_t)(r0 + 8) * N + c] = o1;
        }
    }
}

// ===========================================================================
// HMMA flash attention (causal), split-bf16 (3-pass) for QK^T and PV.
// Grid: (T/128, H, B). Block: 256 threads = 8 warps x 16 q-rows.
// __launch_bounds__(256, 2) for 2 CTAs/SM.
// ===========================================================================
#define QS 72
#define Q_BYTES  (128 * QS * 2)      // 18432
#define KV_BYTES (64 * QS * 2)       // 9216
#define ATTN_SMEM (2 * Q_BYTES + 4 * KV_BYTES)   // 73728

__global__ __launch_bounds__(256, 2) void attn_hmma(
    const float* __restrict__ qkv, float* __restrict__ out)
{
    extern __shared__ char sm[];
    __nv_bfloat16* Qhi  = (__nv_bfloat16*)(sm);
    __nv_bfloat16* Qlo  = (__nv_bfloat16*)(sm + Q_BYTES);
    __nv_bfloat16* Kthi = (__nv_bfloat16*)(sm + 2 * Q_BYTES);
    __nv_bfloat16* Ktlo = (__nv_bfloat16*)(sm + 2 * Q_BYTES + KV_BYTES);
    __nv_bfloat16* Vhi  = (__nv_bfloat16*)(sm + 2 * Q_BYTES + 2 * KV_BYTES);
    __nv_bfloat16* Vlo  = (__nv_bfloat16*)(sm + 2 * Q_BYTES + 3 * KV_BYTES);

    const int tid  = threadIdx.x;
    const int lane = tid & 31;
    const int w    = tid >> 5;
    const int qt = blockIdx.x;
    const int h  = blockIdx.y;
    const int b  = blockIdx.z;
    const int qb = qt * 128;

    const size_t rs = 3 * CC;
    const float* qp0 = qkv + (size_t)b * TT * rs + (size_t)h * HD;

    // ---- load Q tile (128 x 64), split hi/lo ----
#pragma unroll
    for (int i = 0; i < 8; i++) {
        int idx = tid + i * 256;
        int m  = idx >> 4;
        int d4 = (idx & 15) * 4;
        float4 v = *(const float4*)&qp0[(size_t)(qb + m) * rs + d4];
        uint32_t h0, l0, h1, l1;
        split2(v.x, v.y, h0, l0);
        split2(v.z, v.w, h1, l1);
        uint2 hu = { h0, h1 }, lu = { l0, l1 };
        *(uint2*)&Qhi[m * QS + d4] = hu;
        *(uint2*)&Qlo[m * QS + d4] = lu;
    }

    const uint32_t qhiA  = smem_u32(Qhi),  qloA  = smem_u32(Qlo);
    const uint32_t kthiA = smem_u32(Kthi), ktloA = smem_u32(Ktlo);
    const uint32_t vhiA  = smem_u32(Vhi),  vloA  = smem_u32(Vlo);

    float S[8][4];
    float O[8][4] = {};
    float m_run[2] = { -1e30f, -1e30f };
    float l_run[2] = { 0.0f, 0.0f };
    const float scale = 0.125f;

    const int wmin = qb + w * 16;
    const int r_in = lane >> 2;
    const int c2   = (lane & 3) * 2;
    const int row0 = wmin + r_in;
    const int row1 = row0 + 8;

    const int n_tiles = 2 * qt + 2;
    for (int jt = 0; jt < n_tiles; jt++) {
        const int kvb = jt * 64;
        __syncthreads();

        // ---- load K (transposed into [dim][key]) and V ([key][dim]) ----
        const float* kp = qkv + ((size_t)b * TT + kvb) * rs + CC + h * HD;
        const float* vp = kp + CC;
#pragma unroll
        for (int i = 0; i < 4; i++) {
            int idx = tid + i * 256;
            int key = idx >> 4;
            int d4  = (idx & 15) * 4;
            float4 kv4 = *(const float4*)&kp[(size_t)key * rs + d4];
            float ke[4] = { kv4.x, kv4.y, kv4.z, kv4.w };
#pragma unroll
            for (int e = 0; e < 4; e++) {
                float hh = __bfloat162float(__float2bfloat16(ke[e]));
                Kthi[(d4 + e) * QS + key] = __float2bfloat16(hh);
                Ktlo[(d4 + e) * QS + key] = __float2bfloat16(ke[e] - hh);
            }
            float4 vv4 = *(const float4*)&vp[(size_t)key * rs + d4];
            uint32_t h0, l0, h1, l1;
            split2(vv4.x, vv4.y, h0, l0);
            split2(vv4.z, vv4.w, h1, l1);
            uint2 hu = { h0, h1 }, lu = { l0, l1 };
            *(uint2*)&Vhi[key * QS + d4] = hu;
            *(uint2*)&Vlo[key * QS + d4] = lu;
        }
        __syncthreads();

        if (kvb > wmin + 15) continue;   // warp-uniform: tile fully masked for this warp

        // ---- S = Q K^T (3-pass split) ----
#pragma unroll
        for (int nf = 0; nf < 8; nf++)
#pragma unroll
            for (int e = 0; e < 4; e++) S[nf][e] = 0.0f;

#pragma unroll
        for (int ks = 0; ks < 4; ks++) {
            uint32_t qh[4], ql[4];
            uint32_t qoff = ((w * 16 + (lane & 15)) * QS + ks * 16 + (lane >> 4) * 8) * 2;
            LDSM_X4(qh, qhiA + qoff);
            LDSM_X4(ql, qloA + qoff);
#pragma unroll
            for (int np = 0; np < 4; np++) {
                uint32_t kh[4], kl[4];
                uint32_t koff = ((ks * 16 + (lane & 15)) * QS + np * 16 + (lane >> 4) * 8) * 2;
                LDSM_X4T(kh, kthiA + koff);
                LDSM_X4T(kl, ktloA + koff);
                MMA_BF16(S[2*np],   qh, kh);
                MMA_BF16(S[2*np],   qh, kl);
                MMA_BF16(S[2*np],   ql, kh);
                MMA_BF16(S[2*np+1], qh, kh + 2);
                MMA_BF16(S[2*np+1], qh, kl + 2);
                MMA_BF16(S[2*np+1], ql, kh + 2);
            }
        }

        // ---- scale + causal mask + row max ----
        const bool full = (kvb + 63 <= wmin);
        float mx0 = -1e30f, mx1 = -1e30f;
#pragma unroll
        for (int nf = 0; nf < 8; nf++) {
            int col = kvb + nf * 8 + c2;
            float s0 = S[nf][0] * scale;
            float s1 = S[nf][1] * scale;
            float s2 = S[nf][2] * scale;
            float s3 = S[nf][3] * scale;
            if (!full) {
                if (col     > row0) s0 = -1e30f;
                if (col + 1 > row0) s1 = -1e30f;
                if (col     > row1) s2 = -1e30f;
                if (col + 1 > row1) s3 = -1e30f;
            }
            S[nf][0] = s0; S[nf][1] = s1; S[nf][2] = s2; S[nf][3] = s3;
            mx0 = fmaxf(mx0, fmaxf(s0, s1));
            mx1 = fmaxf(mx1, fmaxf(s2, s3));
        }
        mx0 = fmaxf(mx0, __shfl_xor_sync(0xffffffffu, mx0, 1));
        mx0 = fmaxf(mx0, __shfl_xor_sync(0xffffffffu, mx0, 2));
        mx1 = fmaxf(mx1, __shfl_xor_sync(0xffffffffu, mx1, 1));
        mx1 = fmaxf(mx1, __shfl_xor_sync(0xffffffffu, mx1, 2));

        float mn0 = fmaxf(m_run[0], mx0);
        float mn1 = fmaxf(m_run[1], mx1);
        float corr0 = __expf(m_run[0] - mn0);
        float corr1 = __expf(m_run[1] - mn1);
        l_run[0] *= corr0;
        l_run[1] *= corr1;
#pragma unroll
        for (int nf = 0; nf < 8; nf++) {
            O[nf][0] *= corr0; O[nf][1] *= corr0;
            O[nf][2] *= corr1; O[nf][3] *= corr1;
        }

        float sum0 = 0.0f, sum1 = 0.0f;
#pragma unroll
        for (int nf = 0; nf < 8; nf++) {
            float p0 = __expf(S[nf][0] - mn0);
            float p1 = __expf(S[nf][1] - mn0);
            float p2 = __expf(S[nf][2] - mn1);
            float p3 = __expf(S[nf][3] - mn1);
            S[nf][0] = p0; S[nf][1] = p1; S[nf][2] = p2; S[nf][3] = p3;
            sum0 += p0 + p1;
            sum1 += p2 + p3;
        }
        sum0 += __shfl_xor_sync(0xffffffffu, sum0, 1);
        sum0 += __shfl_xor_sync(0xffffffffu, sum0, 2);
        sum1 += __shfl_xor_sync(0xffffffffu, sum1, 1);
        sum1 += __shfl_xor_sync(0xffffffffu, sum1, 2);
        l_run[0] += sum0;
        l_run[1] += sum1;
        m_run[0] = mn0;
        m_run[1] = mn1;

        // ---- O += P V (3-pass split); S frags reinterpret as A frags ----
#pragma unroll
        for (int j = 0; j < 4; j++) {
            uint32_t aH[4], aL[4];
            split2(S[2*j][0],   S[2*j][1],   aH[0], aL[0]);
            split2(S[2*j][2],   S[2*j][3],   aH[1], aL[1]);
            split2(S[2*j+1][0], S[2*j+1][1], aH[2], aL[2]);
            split2(S[2*j+1][2], S[2*j+1][3], aH[3], aL[3]);
#pragma unroll
            for (int np = 0; np < 4; np++) {
                uint32_t vh[4], vl[4];
                uint32_t voff = ((j * 16 + (lane & 15)) * QS + np * 16 + (lane >> 4) * 8) * 2;
                LDSM_X4T(vh, vhiA + voff);
                LDSM_X4T(vl, vloA + voff);
                MMA_BF16(O[2*np],   aH, vh);
                MMA_BF16(O[2*np],   aH, vl);
                MMA_BF16(O[2*np],   aL, vh);
                MMA_BF16(O[2*np+1], aH, vh + 2);
                MMA_BF16(O[2*np+1], aH, vl + 2);
                MMA_BF16(O[2*np+1], aL, vh + 2);
            }
        }
    }

    // ---- epilogue: normalize, write [B,T,C] ----
    float inv0 = 1.0f / l_run[0];
    float inv1 = 1.0f / l_run[1];
    float* o0 = out + ((size_t)b * TT + row0) * CC + h * HD;
    float* o1 = out + ((size_t)b * TT + row1) * CC + h * HD;
#pragma unroll
    for (int nf = 0; nf < 8; nf++) {
        int c = nf * 8 + c2;
        float2 a = { O[nf][0] * inv0, O[nf][1] * inv0 };
        float2 d = { O[nf][2] * inv1, O[nf][3] * inv1 };
        *(float2*)&o0[c] = a;
        *(float2*)&o1[c] = d;
    }
}

// ---------------------------------------------------------------------------
extern "C" void kernel_launch(void* const* d_in, const int* in_sizes, int n_in,
                              void* d_out, int out_size)
{
    const float* x     = (const float*)d_in[0];
    const float* Wqkv  = (const float*)d_in[1];
    const float* bqkv  = (const float*)d_in[2];
    const float* Wproj = (const float*)d_in[3];
    const float* bproj = (const float*)d_in[4];
    float* out = (float*)d_out;

    float *qkv, *att;
    cudaGetSymbolAddress((void**)&qkv, g_qkv);
    cudaGetSymbolAddress((void**)&att, g_att);

    cudaFuncSetAttribute(gemm_hmma,
                         cudaFuncAttributeMaxDynamicSharedMemorySize, GEMM_SMEM);
    cudaFuncSetAttribute(attn_hmma,
                         cudaFuncAttributeMaxDynamicSharedMemorySize, ATTN_SMEM);

    dim3 blk(256);
    // 1) qkv = x @ W_qkv + b_qkv
    gemm_hmma<<<dim3(3 * CC / 128, BT / 128), blk, GEMM_SMEM>>>(x, Wqkv, bqkv, qkv, BT, 3 * CC, CC);
    // 2) attention
    attn_hmma<<<dim3(TT / 128, HH, BB), blk, ATTN_SMEM>>>(qkv, att);
    // 3) out = att @ W_proj + b_proj
    gemm_hmma<<<dim3(CC / 128, BT / 128), blk, GEMM_SMEM>>>(att, Wproj, bproj, out, BT, CC, CC);
}